// round 17
// baseline (speedup 1.0000x reference)
#include <cuda_runtime.h>
#include <math.h>
#include <stdint.h>

#define BATCH 2
#define SQ 2048
#define NH 16
#define DK 64
#define DMODEL 1024
#define NREL 4095

__device__ float g_q[BATCH*NH*SQ*DK];
__device__ float g_k[BATCH*NH*SQ*DK];
__device__ float g_v[BATCH*NH*SQ*DK];
__device__ float g_ctx[(size_t)BATCH*SQ*DMODEL];
__device__ float g_bias[NH*NREL];
__device__ int   g_mask_ones;

// ---------------------------------------------------------------------------
__device__ __forceinline__ float f2tf32(float x) {
    unsigned r;
    asm("cvt.rna.tf32.f32 %0, %1;" : "=r"(r) : "f"(x));
    return __uint_as_float(r);
}

__device__ __forceinline__ void mma_tf32(float c[4], const unsigned* a,
                                         const unsigned* b) {
    asm volatile(
        "mma.sync.aligned.m16n8k8.row.col.f32.tf32.tf32.f32 "
        "{%0,%1,%2,%3}, {%4,%5,%6,%7}, {%8,%9}, {%0,%1,%2,%3};\n"
        : "+f"(c[0]), "+f"(c[1]), "+f"(c[2]), "+f"(c[3])
        : "r"(a[0]), "r"(a[1]), "r"(a[2]), "r"(a[3]), "r"(b[0]), "r"(b[1]));
}

__device__ __forceinline__ uint32_t s2u(const void* p) {
    uint32_t a;
    asm("{ .reg .u64 t; cvta.to.shared.u64 t, %1; cvt.u32.u64 %0, t; }"
        : "=r"(a) : "l"(p));
    return a;
}

__device__ __forceinline__ void ldsm4(unsigned* r, uint32_t addr) {
    asm volatile(
        "ldmatrix.sync.aligned.m8n8.x4.shared.b16 {%0,%1,%2,%3}, [%4];"
        : "=r"(r[0]), "=r"(r[1]), "=r"(r[2]), "=r"(r[3]) : "r"(addr));
}

// ---------------------------------------------------------------------------
__global__ void bias_kernel(const float* __restrict__ emb) {
    int idx = blockIdx.x * blockDim.x + threadIdx.x;
    if (idx >= NREL) return;
    int rel = idx - (SQ - 1);
    int bucket = (rel > 0) ? 16 : 0;
    int rp = rel < 0 ? -rel : rel;
    int add;
    if (rp < 8) {
        add = rp;
    } else {
        float t = logf((float)rp * 0.125f);
        float u = t / 2.772588722239781f;
        float v = u * 8.0f;
        int w = 8 + (int)v;
        add = w < 15 ? w : 15;
    }
    bucket += add;
#pragma unroll
    for (int h = 0; h < NH; h++)
        g_bias[h * NREL + idx] = emb[bucket * NH + h];
}

__global__ void flag_init_kernel() { g_mask_ones = 1; }

__global__ void mask_check_kernel(const float* __restrict__ mask) {
    size_t t = (size_t)blockIdx.x * blockDim.x + threadIdx.x;
    const float4* p = (const float4*)mask + t * 4;
    bool ok = true;
#pragma unroll
    for (int i = 0; i < 4; i++) {
        float4 v = p[i];
        ok &= (v.x == 1.0f) & (v.y == 1.0f) & (v.z == 1.0f) & (v.w == 1.0f);
    }
    if (!__all_sync(0xffffffffu, ok)) {
        if ((threadIdx.x & 31) == 0) atomicExch(&g_mask_ones, 0);
    }
}

// ---------------------------------------------------------------------------
// TF32 GEMM: BK=32, 2-stage, half-tile loads interleaved with mma.
// CTA 128x128, 256 thr, 8 warps (2x4), warp tile 64x32. Same K-chunk order
// as BK=16 version -> bitwise-identical accumulation.
// ---------------------------------------------------------------------------
#define AP2 36
#define BP 136
#define ASW (128 * AP2)   // 4608 words / stage
#define BSW (32 * BP)     // 4352 words / stage

template <int NSZ, int MODE>
__global__ __launch_bounds__(256)
void gemm_tc(const float* __restrict__ A, const float* __restrict__ B,
             float* __restrict__ Cout) {
    extern __shared__ __align__(16) float smf[];

    const int n0 = blockIdx.x * 128;
    const int m0 = blockIdx.y * 128;
    const int tid = threadIdx.x;
    const int warp = tid >> 5, lane = tid & 31;
    const int wy = warp >> 2, wx = warp & 3;
    const int lr = lane >> 2, lc = lane & 3;

    const int a_lrow = (lane & 7) + ((lane >> 3) & 1) * 8;
    const int a_lcol = ((lane >> 4) & 1) * 4;

    const float* Abase = (MODE == 0) ? A : (const float*)g_ctx;
    const float* Ap = Abase + (size_t)m0 * 1024;
    const float* Bp = B + n0;

    // Loaders: A 128x32, thread -> row tid>>1, 16-col chunk (tid&1)*16
    //          B 32x128, thread -> row tid>>3, 16-col chunk (tid&7)*16
    const int a_row = tid >> 1, a_cb = (tid & 1) * 16;
    const int b_row = tid >> 3, b_cb = (tid & 7) * 16;

    float acc[4][4][4];
#pragma unroll
    for (int i = 0; i < 4; i++)
#pragma unroll
        for (int j = 0; j < 4; j++)
#pragma unroll
            for (int r = 0; r < 4; r++) acc[i][j][r] = 0.f;

    float4 pa0, pa1, pb0, pb1;

#define LOADH(k0, h)                                                          \
    do {                                                                      \
        pa0 = *(const float4*)(Ap + (size_t)a_row * 1024 + (k0) + a_cb + (h) * 8);     \
        pa1 = *(const float4*)(Ap + (size_t)a_row * 1024 + (k0) + a_cb + (h) * 8 + 4); \
        pb0 = *(const float4*)(Bp + (size_t)((k0) + b_row) * NSZ + b_cb + (h) * 8);    \
        pb1 = *(const float4*)(Bp + (size_t)((k0) + b_row) * NSZ + b_cb + (h) * 8 + 4);\
    } while (0)

#define STOREH(st, h)                                                         \
    do {                                                                      \
        float* as_ = smf + (st) * ASW;                                        \
        float* bs_ = smf + 2 * ASW + (st) * BSW;                              \
        int ao = a_row * AP2 + a_cb + (h) * 8;                                \
        int bo = b_row * BP + b_cb + (h) * 8;                                 \
        as_[ao + 0] = f2tf32(pa0.x); as_[ao + 1] = f2tf32(pa0.y);             \
        as_[ao + 2] = f2tf32(pa0.z); as_[ao + 3] = f2tf32(pa0.w);             \
        as_[ao + 4] = f2tf32(pa1.x); as_[ao + 5] = f2tf32(pa1.y);             \
        as_[ao + 6] = f2tf32(pa1.z); as_[ao + 7] = f2tf32(pa1.w);             \
        bs_[bo + 0] = f2tf32(pb0.x); bs_[bo + 1] = f2tf32(pb0.y);             \
        bs_[bo + 2] = f2tf32(pb0.z); bs_[bo + 3] = f2tf32(pb0.w);             \
        bs_[bo + 4] = f2tf32(pb1.x); bs_[bo + 5] = f2tf32(pb1.y);             \
        bs_[bo + 6] = f2tf32(pb1.z); bs_[bo + 7] = f2tf32(pb1.w);             \
    } while (0)

#define MMAKS(ks)                                                             \
    do {                                                                      \
        const uint32_t asb = s2u(smf) + (uint32_t)(s * ASW) * 4u;             \
        const float* bs_ = smf + 2 * ASW + s * BSW;                           \
        unsigned af[4][4], bf[4][2];                                          \
        _Pragma("unroll")                                                     \
        for (int mt = 0; mt < 4; mt++)                                        \
            ldsm4(af[mt], asb + (uint32_t)((wy * 64 + mt * 16 + a_lrow) * AP2 \
                                          + (ks) * 8 + a_lcol) * 4u);         \
        _Pragma("unroll")                                                     \
        for (int nt = 0; nt < 4; nt++) {                                      \
            int n = wx * 32 + nt * 8 + lr;                                    \
            bf[nt][0] = __float_as_uint(bs_[((ks) * 8 + lc) * BP + n]);       \
            bf[nt][1] = __float_as_uint(bs_[((ks) * 8 + lc + 4) * BP + n]);   \
        }                                                                     \
        _Pragma("unroll")                                                     \
        for (int mt = 0; mt < 4; mt++)                                        \
            _Pragma("unroll")                                                 \
            for (int nt = 0; nt < 4; nt++)                                    \
                mma_tf32(acc[mt][nt], af[mt], bf[nt]);                        \
    } while (0)

    // Prologue: tile 0 into stage 0
    LOADH(0, 0); STOREH(0, 0);
    LOADH(0, 1); STOREH(0, 1);

    int s = 0;
    for (int it = 0; it < 32; it++) {
        __syncthreads();
        const int kn = (it + 1) * 32;
        const bool more = it < 31;
        if (more) LOADH(kn, 0);
        MMAKS(0);
        MMAKS(1);
        if (more) { STOREH(s ^ 1, 0); LOADH(kn, 1); }
        MMAKS(2);
        if (more) STOREH(s ^ 1, 1);
        MMAKS(3);
        s ^= 1;
    }
#undef LOADH
#undef STOREH
#undef MMAKS

#pragma unroll
    for (int mt = 0; mt < 4; mt++) {
        int gm0 = m0 + wy * 64 + mt * 16 + lr;
#pragma unroll
        for (int nt = 0; nt < 4; nt++) {
            int gn = n0 + wx * 32 + nt * 8 + 2 * lc;
            if (MODE == 1) {
                *(float2*)(Cout + (size_t)gm0 * NSZ + gn) =
                    make_float2(acc[mt][nt][0], acc[mt][nt][1]);
                *(float2*)(Cout + (size_t)(gm0 + 8) * NSZ + gn) =
                    make_float2(acc[mt][nt][2], acc[mt][nt][3]);
            } else {
                const int part = gn >> 10;
                const int h = (gn & 1023) >> 6;
                const int d = gn & 63;
                float* dst = (part == 0) ? g_q : (part == 1) ? g_k : g_v;
                {
                    int b = gm0 >> 11, sq = gm0 & 2047;
                    float* row = dst + ((size_t)((b * NH + h) * SQ) + sq) * DK;
                    *(float2*)(row + d) =
                        make_float2(f2tf32(acc[mt][nt][0]), f2tf32(acc[mt][nt][1]));
                }
                {
                    int gm1 = gm0 + 8;
                    int b = gm1 >> 11, sq = gm1 & 2047;
                    float* row = dst + ((size_t)((b * NH + h) * SQ) + sq) * DK;
                    *(float2*)(row + d) =
                        make_float2(f2tf32(acc[mt][nt][2]), f2tf32(acc[mt][nt][3]));
                }
            }
        }
    }
}

// ---------------------------------------------------------------------------
// Flash attention (R15 body, unchanged): ldmatrix Q/K, raw K/V copies,
// all-ones mask fast path.
// ---------------------------------------------------------------------------
#define BQ 128
#define BKV 64
#define QP 68
#define KP 68
#define VP 72

__global__ __launch_bounds__(256)
void attn_tc(const float* __restrict__ mask) {
    extern __shared__ float sm[];
    float* Qs  = sm;
    float* Ks  = Qs + BQ * QP;
    float* Vs  = Ks + BKV * KP;
    float* Bsm = Vs + BKV * VP;

    const int q0 = blockIdx.x * BQ;
    const int h  = blockIdx.y;
    const int b  = blockIdx.z;
    const int tid = threadIdx.x;
    const int warp = tid >> 5, lane = tid & 31;
    const int lr = lane >> 2, lc = lane & 3;
    const int r0 = warp * 16 + lr;
    const int r1 = r0 + 8;

    const int a_lrow = (lane & 7) + ((lane >> 3) & 1) * 8;
    const int a_lcol = ((lane >> 4) & 1) * 4;
    const int k_lrow = (lane & 7) + ((lane >> 4) & 1) * 8;
    const int k_lcol = ((lane >> 3) & 1) * 4;
    const uint32_t sbQ = s2u(Qs);
    const uint32_t sbK = s2u(Ks);

    const float* Qg = g_q + ((size_t)(b * NH + h) * SQ + q0) * DK;
    const float* Kg = g_k + (size_t)(b * NH + h) * SQ * DK;
    const float* Vg = g_v + (size_t)(b * NH + h) * SQ * DK;
    const float* Mg = mask + (size_t)b * SQ * SQ;
    const float* Bg = g_bias + h * NREL;

    const bool mask_ones = (g_mask_ones != 0);

#pragma unroll
    for (int t = 0; t < 8; t++) {
        int f = tid + t * 256;
        int r = f >> 4, c4 = (f & 15) * 4;
        *(float4*)(&Qs[r * QP + c4]) = *(const float4*)(Qg + r * DK + c4);
    }

    float m0 = -3.0e38f, m1 = -3.0e38f, l0 = 0.f, l1 = 0.f;
    float o[8][4];
#pragma unroll
    for (int nt = 0; nt < 8; nt++)
#pragma unroll
        for (int r = 0; r < 4; r++) o[nt][r] = 0.f;

    const unsigned FULL = 0xffffffffu;
    const int src0 = (lane & 28) | (lc >> 1);
    const int src1 = src0 + 2;
    const bool odd = (lc & 1) != 0;

    for (int k0 = 0; k0 < SQ; k0 += BKV) {
        __syncthreads();
#pragma unroll
        for (int t = 0; t < 4; t++) {
            int f = tid + t * 256;
            int r = f >> 4, c4 = (f & 15) * 4;
            *(float4*)(&Ks[r * KP + c4]) =
                *(const float4*)(Kg + (size_t)(k0 + r) * DK + c4);
            *(float4*)(&Vs[r * VP + c4]) =
                *(const float4*)(Vg + (size_t)(k0 + r) * DK + c4);
        }
        if (tid < 191)
            Bsm[tid] = Bg[k0 - q0 + tid - 127 + (SQ - 1)];
        __syncthreads();

        float sc[8][4];
#pragma unroll
        for (int nt = 0; nt < 8; nt++)
#pragma unroll
            for (int r = 0; r < 4; r++) sc[nt][r] = 0.f;

#pragma unroll
        for (int ks = 0; ks < 8; ks++) {
            unsigned af[4], kf[4][4];
            ldsm4(af, sbQ + (uint32_t)((warp * 16 + a_lrow) * QP
                                       + ks * 8 + a_lcol) * 4u);
#pragma unroll
            for (int p = 0; p < 4; p++)
                ldsm4(kf[p], sbK + (uint32_t)((p * 16 + k_lrow) * KP
                                              + ks * 8 + k_lcol) * 4u);
#pragma unroll
            for (int p = 0; p < 4; p++) {
                mma_tf32(sc[2 * p + 0], af, &kf[p][0]);
                mma_tf32(sc[2 * p + 1], af, &kf[p][2]);
            }
        }

        if (mask_ones) {
#pragma unroll
            for (int nt = 0; nt < 8; nt++) {
                int col = nt * 8 + 2 * lc;
                float b00 = Bsm[col - r0 + 127];
                float b01 = Bsm[col + 1 - r0 + 127];
                float b10 = Bsm[col - r1 + 127];
                float b11 = Bsm[col + 1 - r1 + 127];
                sc[nt][0] = __fadd_rn(__fmul_rn(sc[nt][0], 0.125f), b00);
                sc[nt][1] = __fadd_rn(__fmul_rn(sc[nt][1], 0.125f), b01);
                sc[nt][2] = __fadd_rn(__fmul_rn(sc[nt][2], 0.125f), b10);
                sc[nt][3] = __fadd_rn(__fmul_rn(sc[nt][3], 0.125f), b11);
            }
        } else {
            int gq0 = q0 + r0, gq1 = q0 + r1;
#pragma unroll
            for (int nt = 0; nt < 8; nt++) {
                int col = nt * 8 + 2 * lc;
                int kg = k0 + col;
                float2 mv0 = *(const float2*)(Mg + (size_t)gq0 * SQ + kg);
                float2 mv1 = *(const float2*)(Mg + (size_t)gq1 * SQ + kg);
                float b00 = Bsm[col - r0 + 127];
                float b01 = Bsm[col + 1 - r0 + 127];
                float b10 = Bsm[col - r1 + 127];
                float b11 = Bsm[col + 1 - r1 + 127];
                sc[nt][0] = sc[nt][0] * 0.125f * mv0.x + (b00 - 10000.f * (1.f - mv0.x));
                sc[nt][1] = sc[nt][1] * 0.125f * mv0.y + (b01 - 10000.f * (1.f - mv0.y));
                sc[nt][2] = sc[nt][2] * 0.125f * mv1.x + (b10 - 10000.f * (1.f - mv1.x));
                sc[nt][3] = sc[nt][3] * 0.125f * mv1.y + (b11 - 10000.f * (1.f - mv1.y));
            }
        }

        float tm0 = -3.0e38f, tm1 = -3.0e38f;
#pragma unroll
        for (int nt = 0; nt < 8; nt++) {
            tm0 = fmaxf(tm0, fmaxf(sc[nt][0], sc[nt][1]));
            tm1 = fmaxf(tm1, fmaxf(sc[nt][2], sc[nt][3]));
        }
        tm0 = fmaxf(tm0, __shfl_xor_sync(FULL, tm0, 1));
        tm0 = fmaxf(tm0, __shfl_xor_sync(FULL, tm0, 2));
        tm1 = fmaxf(tm1, __shfl_xor_sync(FULL, tm1, 1));
        tm1 = fmaxf(tm1, __shfl_xor_sync(FULL, tm1, 2));
        float mn0 = fmaxf(m0, tm0), mn1 = fmaxf(m1, tm1);
        float al0 = __expf(m0 - mn0), al1 = __expf(m1 - mn1);
        m0 = mn0; m1 = mn1;
        float ps0 = 0.f, ps1 = 0.f;
#pragma unroll
        for (int nt = 0; nt < 8; nt++) {
            float e0 = __expf(sc[nt][0] - mn0);
            float e1 = __expf(sc[nt][1] - mn0);
            float e2 = __expf(sc[nt][2] - mn1);
            float e3 = __expf(sc[nt][3] - mn1);
            ps0 += e0 + e1; ps1 += e2 + e3;
            sc[nt][0] = f2tf32(e0); sc[nt][1] = f2tf32(e1);
            sc[nt][2] = f2tf32(e2); sc[nt][3] = f2tf32(e3);
        }
        ps0 += __shfl_xor_sync(FULL, ps0, 1);
        ps0 += __shfl_xor_sync(FULL, ps0, 2);
        ps1 += __shfl_xor_sync(FULL, ps1, 1);
        ps1 += __shfl_xor_sync(FULL, ps1, 2);
        l0 = l0 * al0 + ps0;
        l1 = l1 * al1 + ps1;

#pragma unroll
        for (int nt = 0; nt < 8; nt++) {
            o[nt][0] *= al0; o[nt][1] *= al0;
            o[nt][2] *= al1; o[nt][3] *= al1;
        }

#pragma unroll
        for (int ks = 0; ks < 8; ks++) {
            float t00 = __shfl_sync(FULL, sc[ks][0], src0);
            float t01 = __shfl_sync(FULL, sc[ks][1], src0);
            float t10 = __shfl_sync(FULL, sc[ks][2], src0);
            float t11 = __shfl_sync(FULL, sc[ks][3], src0);
            float u00 = __shfl_sync(FULL, sc[ks][0], src1);
            float u01 = __shfl_sync(FULL, sc[ks][1], src1);
            float u10 = __shfl_sync(FULL, sc[ks][2], src1);
            float u11 = __shfl_sync(FULL, sc[ks][3], src1);
            unsigned af[4];
            af[0] = __float_as_uint(odd ? t01 : t00);
            af[1] = __float_as_uint(odd ? t11 : t10);
            af[2] = __float_as_uint(odd ? u01 : u00);
            af[3] = __float_as_uint(odd ? u11 : u10);
#pragma unroll
            for (int nt = 0; nt < 8; nt++) {
                int d = nt * 8 + lr;
                unsigned bf[2];
                bf[0] = __float_as_uint(Vs[(ks * 8 + lc) * VP + d]);
                bf[1] = __float_as_uint(Vs[(ks * 8 + lc + 4) * VP + d]);
                mma_tf32(o[nt], af, bf);
            }
        }
    }

    {
        float li0 = 1.0f / l0, li1 = 1.0f / l1;
        int gq0 = q0 + r0, gq1 = q0 + r1;
#pragma unroll
        for (int nt = 0; nt < 8; nt++) {
            int d = h * DK + nt * 8 + 2 * lc;
            *(float2*)(g_ctx + (size_t)(b * SQ + gq0) * DMODEL + d) =
                make_float2(o[nt][0] * li0, o[nt][1] * li0);
            *(float2*)(g_ctx + (size_t)(b * SQ + gq1) * DMODEL + d) =
                make_float2(o[nt][2] * li1, o[nt][3] * li1);
        }
    }
}

// ---------------------------------------------------------------------------
extern "C" void kernel_launch(void* const* d_in, const int* in_sizes, int n_in,
                              void* d_out, int out_size) {
    (void)in_sizes; (void)n_in; (void)out_size;
    const float* hidden = (const float*)d_in[0];
    const float* mask   = (const float*)d_in[1];
    const float* Wqkv   = (const float*)d_in[2];
    const float* Wo     = (const float*)d_in[3];
    const float* emb    = (const float*)d_in[4];
    float* out = (float*)d_out;

    bias_kernel<<<16, 256>>>(emb);
    flag_init_kernel<<<1, 1>>>();
    mask_check_kernel<<<2048, 256>>>(mask);

    const int gsm = (2 * ASW + 2 * BSW) * 4;  // 71680 B
    cudaFuncSetAttribute(gemm_tc<3072, 0>, cudaFuncAttributeMaxDynamicSharedMemorySize, gsm);
    cudaFuncSetAttribute(gemm_tc<1024, 1>, cudaFuncAttributeMaxDynamicSharedMemorySize, gsm);

    gemm_tc<3072, 0><<<dim3(24, 32), 256, gsm>>>(hidden, Wqkv, nullptr);

    const int smem_bytes = (BQ * QP + BKV * KP + BKV * VP + 192) * 4;
    cudaFuncSetAttribute(attn_tc, cudaFuncAttributeMaxDynamicSharedMemorySize,
                         smem_bytes);
    attn_tc<<<dim3(SQ / BQ, NH, BATCH), 256, smem_bytes>>>(mask);

    gemm_tc<1024, 1><<<dim3(8, 32), 256, gsm>>>(nullptr, Wo, out);
}